// round 6
// baseline (speedup 1.0000x reference)
#include <cuda_runtime.h>
#include <cuda_bf16.h>
#include <math.h>
#include <stdint.h>

// Problem constants
#define B_   16
#define Hh   8
#define T_   48
#define Np   16
#define C_   512
#define D_   64
#define L_   768           // Np * T_
#define M_   (B_ * L_)     // 12288 rows

// Scratch — all tf32 bit patterns (converted at producer side)
__device__ uint32_t g_q[(size_t)B_ * Hh * D_ * L_];   // [b][h][d][l']  (t-major l')
__device__ uint32_t g_k[(size_t)B_ * Hh * D_ * L_];   // [b][h][d][l']
__device__ uint32_t g_v[(size_t)B_ * Hh * L_ * D_];   // [b][h][l'][d]
__device__ uint32_t g_y[(size_t)B_ * L_ * C_];        // [b][l][c]  (original l order)

__device__ __forceinline__ uint32_t f2tf(float f) {
    uint32_t u;
    asm("cvt.rna.tf32.f32 %0, %1;" : "=r"(u) : "f"(f));
    return u;
}

__device__ __forceinline__ void mma_tf32(float* d, const uint32_t* a, const uint32_t* b) {
    asm volatile(
        "mma.sync.aligned.m16n8k8.row.col.f32.tf32.tf32.f32 "
        "{%0,%1,%2,%3}, {%4,%5,%6,%7}, {%8,%9}, {%0,%1,%2,%3};"
        : "+f"(d[0]), "+f"(d[1]), "+f"(d[2]), "+f"(d[3])
        : "r"(a[0]), "r"(a[1]), "r"(a[2]), "r"(a[3]), "r"(b[0]), "r"(b[1]));
}

#define ASZ 4224            // 8*4*132 words per stage
#define BSZ 4096            // 16*4*64 words per stage
#define GSMEM_BYTES ((ASZ + BSZ) * 2 * 4)

// ---------------------------------------------------------------------------
// Double-buffered tensor-core tf32 GEMM, fragment-native A and B smem layouts.
// MODE 0: out = g_y(tf32 bits) @ W0        grid (4, 96)
// MODE 1: fused QKV: x @ {Wq,Wk,Wv}        grid (12, 96), wsel = n0g>>9
// Block 128 threads (4 warps 2x2), tile 128x128, K-step 32, 16 iters, 1 sync/iter.
// ---------------------------------------------------------------------------
template <int MODE>
__global__ __launch_bounds__(128) void gemm_tc(const float* __restrict__ X,
                                               const float* __restrict__ W0,
                                               const float* __restrict__ W1,
                                               const float* __restrict__ W2,
                                               float* __restrict__ Cout) {
    extern __shared__ uint32_t sm[];
    uint32_t* const Asb[2] = { sm, sm + ASZ };
    uint32_t* const Bsb[2] = { sm + 2 * ASZ, sm + 2 * ASZ + BSZ };

    const int n0g = blockIdx.x * 128;
    const float* W;
    int wsel = 0;
    if (MODE == 1) {
        wsel = n0g >> 9;
        W = (wsel == 0) ? W0 : (wsel == 1) ? W1 : W2;
    } else {
        W = W0;
    }
    const int n0 = (MODE == 1) ? (n0g & 511) : n0g;
    const int m0 = blockIdx.y * 128;

    const int tid = threadIdx.x;
    const int lane = tid & 31;
    const int w = tid >> 5;
    const int wr = w & 1;
    const int wc = w >> 1;
    const int r = lane >> 2;
    const int c = lane & 3;

    float acc[4][8][4] = {};

    // A-load mapping
    const int s_a = tid >> 3;           // 0..15
    const int c4_a = (tid & 7) * 4;     // 0..28
    const int a_chunk = (tid & 7) >> 1;
    const int a_val = (s_a >> 3) + 2 * (tid & 1);
    const int a_lanebase = (s_a & 7) * 16;

    // B-load mapping (fragment-native, attn-style)
    const int ld_bn = tid & 15;         // column group (8 cols)
    const int ld_bs = tid >> 4;         // 0..7 (row within 8-row band)
    const int b_cc2 = (ld_bs & 3) * 2;
    const int b_val = ld_bs >> 2;
    const int b_xor = 8 * (ld_bn & 3);

    uint4 aU[8], bU[8];

    // prologue: load k0 = 0
#pragma unroll
    for (int f = 0; f < 8; f++) {
        if (MODE == 0) {
            aU[f] = *(const uint4*)&g_y[(size_t)(m0 + f * 16 + s_a) * C_ + c4_a];
        } else {
            float4 v = *(const float4*)&X[(size_t)(m0 + f * 16 + s_a) * C_ + c4_a];
            aU[f] = make_uint4(f2tf(v.x), f2tf(v.y), f2tf(v.z), f2tf(v.w));
        }
    }
#pragma unroll
    for (int it = 0; it < 4; it++) {
        float4 v0 = *(const float4*)&W[(size_t)(it * 8 + ld_bs) * C_ + n0 + ld_bn * 8];
        float4 v1 = *(const float4*)&W[(size_t)(it * 8 + ld_bs) * C_ + n0 + ld_bn * 8 + 4];
        bU[it * 2]     = make_uint4(f2tf(v0.x), f2tf(v0.y), f2tf(v0.z), f2tf(v0.w));
        bU[it * 2 + 1] = make_uint4(f2tf(v1.x), f2tf(v1.y), f2tf(v1.z), f2tf(v1.w));
    }

#pragma unroll 1
    for (int itk = 0; itk < 16; itk++) {
        const int st = itk & 1;
        uint32_t* const As = Asb[st];
        uint32_t* const Bs = Bsb[st];

        // STS from prefetch regs
#pragma unroll
        for (int f = 0; f < 8; f++) {
            const uint32_t av[4] = {aU[f].x, aU[f].y, aU[f].z, aU[f].w};
            const int abase = (f * 4 + a_chunk) * 132 + a_lanebase + a_val;
#pragma unroll
            for (int j = 0; j < 4; j++) As[abase + j * 4] = av[j];
        }
#pragma unroll
        for (int it = 0; it < 4; it++) {
            const uint32_t bv[8] = {bU[it*2].x, bU[it*2].y, bU[it*2].z, bU[it*2].w,
                                    bU[it*2+1].x, bU[it*2+1].y, bU[it*2+1].z, bU[it*2+1].w};
            const int wb = (ld_bn * 4 + it) * 64 + b_val;
#pragma unroll
            for (int j = 0; j < 8; j++) Bs[wb + ((8 * j + b_cc2) ^ b_xor)] = bv[j];
        }
        __syncthreads();

        // prefetch next k-step
        if (itk < 15) {
            const int k1 = (itk + 1) * 32;
#pragma unroll
            for (int f = 0; f < 8; f++) {
                if (MODE == 0) {
                    aU[f] = *(const uint4*)&g_y[(size_t)(m0 + f * 16 + s_a) * C_ + k1 + c4_a];
                } else {
                    float4 v = *(const float4*)&X[(size_t)(m0 + f * 16 + s_a) * C_ + k1 + c4_a];
                    aU[f] = make_uint4(f2tf(v.x), f2tf(v.y), f2tf(v.z), f2tf(v.w));
                }
            }
#pragma unroll
            for (int it = 0; it < 4; it++) {
                float4 v0 = *(const float4*)&W[(size_t)(k1 + it * 8 + ld_bs) * C_ + n0 + ld_bn * 8];
                float4 v1 = *(const float4*)&W[(size_t)(k1 + it * 8 + ld_bs) * C_ + n0 + ld_bn * 8 + 4];
                bU[it * 2]     = make_uint4(f2tf(v0.x), f2tf(v0.y), f2tf(v0.z), f2tf(v0.w));
                bU[it * 2 + 1] = make_uint4(f2tf(v1.x), f2tf(v1.y), f2tf(v1.z), f2tf(v1.w));
            }
        }

        // compute 4 k-steps of 8
#pragma unroll
        for (int ks = 0; ks < 4; ks++) {
            uint4 afr[4];
#pragma unroll
            for (int mi = 0; mi < 4; mi++)
                afr[mi] = *(const uint4*)&As[((wr * 4 + mi) * 4 + ks) * 132 + lane * 4];
            uint2 bfr[8];
#pragma unroll
            for (int ni = 0; ni < 8; ni++) {
                const int ng = wc * 8 + ni;
                bfr[ni] = *(const uint2*)&Bs[(ng * 4 + ks) * 64 + ((lane * 2) ^ (8 * (ng & 3)))];
            }
#pragma unroll
            for (int mi = 0; mi < 4; mi++)
#pragma unroll
                for (int ni = 0; ni < 8; ni++)
                    mma_tf32(acc[mi][ni], (const uint32_t*)&afr[mi], (const uint32_t*)&bfr[ni]);
        }
        __syncthreads();
    }

    const float scale = (MODE == 1 && wsel == 0) ? 0.125f : 1.0f;
    const int c2 = c * 2;

#pragma unroll
    for (int mi = 0; mi < 4; mi++) {
#pragma unroll
        for (int ni = 0; ni < 8; ni++) {
#pragma unroll
            for (int e = 0; e < 4; e++) {
                const int m = m0 + wr * 64 + mi * 16 + r + (e >> 1) * 8;
                const int cc = n0 + wc * 64 + ni * 8 + c2 + (e & 1);
                const float val = acc[mi][ni][e] * scale;
                if (MODE == 0) {
                    Cout[(size_t)m * C_ + cc] = val;
                } else {
                    const int b = m / L_;
                    const int l = m - b * L_;
                    const int n = l / T_;
                    const int t = l - n * T_;
                    const int lp = t * Np + n;
                    const int h = cc >> 6;
                    const int d = cc & 63;
                    if (wsel == 0)
                        g_q[(((size_t)(b * Hh + h)) * D_ + d) * L_ + lp] = f2tf(val);
                    else if (wsel == 1)
                        g_k[(((size_t)(b * Hh + h)) * D_ + d) * L_ + lp] = f2tf(val);
                    else
                        g_v[(((size_t)(b * Hh + h)) * L_ + lp) * D_ + d] = f2tf(val);
                }
            }
        }
    }
}

// ---------------------------------------------------------------------------
// Tensor-core flash attention; q/k/v arrive as tf32 bits (no cvt on load).
// Grid: (12 q-tiles, 128 bh). Block: 128 threads (4 warps, 16 q-rows each).
// ---------------------------------------------------------------------------
__global__ __launch_bounds__(128) void attn_tc(const float* __restrict__ bt_tab,
                                               const float* __restrict__ bp_tab) {
    __shared__ uint32_t KPs[4096];   // K-frag; later P-frag
    __shared__ uint32_t Vs[4096];    // V-frag
    __shared__ float bt_s[95];
    __shared__ float bp_s[31];

    const int qt = 11 - blockIdx.x;    // long blocks first
    const int bh = blockIdx.y;
    const int b = bh >> 3;
    const int h = bh & 7;

    const uint32_t* qg = g_q + (size_t)bh * D_ * L_;
    const uint32_t* kg = g_k + (size_t)bh * D_ * L_;
    const uint32_t* vg = g_v + (size_t)bh * L_ * D_;

    const int tid = threadIdx.x;
    const int lane = tid & 31;
    const int w = tid >> 5;
    const int r = lane >> 2;   // 0..7
    const int c = lane & 3;    // 0..3

    if (tid < 95) bt_s[tid] = bt_tab[tid * Hh + h];
    if (tid < 31) bp_s[tid] = bp_tab[tid * Hh + h];

    const int row0 = qt * 64 + w * 16 + r;
    const int row1 = row0 + 8;
    const int tq0 = row0 >> 4, nq0 = row0 & 15;
    const int tq1 = row1 >> 4, nq1 = row1 & 15;

    // Q fragments (raw tf32 bits)
    uint32_t qf[8][4];
#pragma unroll
    for (int ks = 0; ks < 8; ks++) {
        const int d0 = ks * 8 + c;
        qf[ks][0] = qg[(size_t)d0 * L_ + row0];
        qf[ks][1] = qg[(size_t)d0 * L_ + row1];
        qf[ks][2] = qg[(size_t)(d0 + 4) * L_ + row0];
        qf[ks][3] = qg[(size_t)(d0 + 4) * L_ + row1];
    }

    // loader-thread constants
    const int ld_s = tid >> 3;          // 0..15
    const int ld_ni = tid & 7;          // column group
    const int ld_c8 = ld_ni * 8;
    const int ld_xor = 8 * (ld_ni & 3);

    float m0 = -1e30f, m1 = -1e30f;
    float l0 = 0.0f, l1 = 0.0f;
    float o[8][4] = {};

    // prefetch kt=0 tiles
    uint4 kR[8], vR[8];
#pragma unroll
    for (int it = 0; it < 4; it++) {
        const int rr = it * 16 + ld_s;
        kR[it * 2]     = *(const uint4*)&kg[(size_t)rr * L_ + ld_c8];
        kR[it * 2 + 1] = *(const uint4*)&kg[(size_t)rr * L_ + ld_c8 + 4];
        vR[it * 2]     = *(const uint4*)&vg[(size_t)rr * D_ + ld_c8];
        vR[it * 2 + 1] = *(const uint4*)&vg[(size_t)rr * D_ + ld_c8 + 4];
    }

    __syncthreads();   // bias tables visible

    const uint32_t pSwz = (uint32_t)(lane * 4) ^ ((uint32_t)(r & 7) << 2);
    const uint32_t kSwz = (uint32_t)(lane * 2);

    for (int kt = 0; kt <= qt; kt++) {
        // STS K/V fragments from prefetch regs
#pragma unroll
        for (int it = 0; it < 4; it++) {
            const int rr = it * 16 + ld_s;
            const int ks = rr >> 3;
            const int dc = rr & 7;
            const int cc2 = (dc & 3) * 2;
            const int val = dc >> 2;
            const int kbase = (ld_ni * 8 + ks) * 64 + val;
            const uint32_t kv[8] = {kR[it*2].x, kR[it*2].y, kR[it*2].z, kR[it*2].w,
                                    kR[it*2+1].x, kR[it*2+1].y, kR[it*2+1].z, kR[it*2+1].w};
            const uint32_t vv[8] = {vR[it*2].x, vR[it*2].y, vR[it*2].z, vR[it*2].w,
                                    vR[it*2+1].x, vR[it*2+1].y, vR[it*2+1].z, vR[it*2+1].w};
#pragma unroll
            for (int j = 0; j < 8; j++) {
                const int off = ((8 * j + cc2) ^ ld_xor);
                KPs[kbase + off] = kv[j];
                Vs[kbase + off] = vv[j];
            }
        }
        __syncthreads();

        // prefetch next tile
        if (kt < qt) {
            const int kn = (kt + 1) * 64;
#pragma unroll
            for (int it = 0; it < 4; it++) {
                const int rr = it * 16 + ld_s;
                kR[it * 2]     = *(const uint4*)&kg[(size_t)rr * L_ + kn + ld_c8];
                kR[it * 2 + 1] = *(const uint4*)&kg[(size_t)rr * L_ + kn + ld_c8 + 4];
                vR[it * 2]     = *(const uint4*)&vg[(size_t)(kn + rr) * D_ + ld_c8];
                vR[it * 2 + 1] = *(const uint4*)&vg[(size_t)(kn + rr) * D_ + ld_c8 + 4];
            }
        }

        // S = Q K
        float s[8][4] = {};
#pragma unroll
        for (int ks = 0; ks < 8; ks++) {
#pragma unroll
            for (int ni = 0; ni < 8; ni++) {
                uint2 bf = *(const uint2*)&KPs[(ni * 8 + ks) * 64 + (kSwz ^ (8 * (ni & 3)))];
                mma_tf32(s[ni], qf[ks], (const uint32_t*)&bf);
            }
        }

        // Bias + causal mask (mask only on diagonal tile)
        const bool diag = (kt == qt);
#pragma unroll
        for (int ni = 0; ni < 8; ni++) {
#pragma unroll
            for (int e = 0; e < 4; e++) {
                const int col = ni * 8 + c * 2 + (e & 1);
                const int lpk = kt * 64 + col;
                const int tk = lpk >> 4;
                const int nk = lpk & 15;
                const int tq = (e < 2) ? tq0 : tq1;
                const int nq = (e < 2) ? nq0 : nq1;
                s[ni][e] += bt_s[47 + tk - tq] + bp_s[15 + nk - nq];
                if (diag && tk > tq) s[ni][e] = -1e30f;
            }
        }

        // Online softmax
        float mx0 = -1e30f, mx1 = -1e30f;
#pragma unroll
        for (int ni = 0; ni < 8; ni++) {
            mx0 = fmaxf(mx0, fmaxf(s[ni][0], s[ni][1]));
            mx1 = fmaxf(mx1, fmaxf(s[ni][2], s[ni][3]));
        }
        mx0 = fmaxf(mx0, __shfl_xor_sync(0xffffffffu, mx0, 1));
        mx0 = fmaxf(mx0, __shfl_xor_sync(0xffffffffu, mx0, 2));
        mx1 = fmaxf(mx1, __shfl_xor_sync(0xffffffffu, mx1, 1));
        mx1 = fmaxf(mx1, __shfl_xor_sync(0xffffffffu, mx1, 2));

        const float mn0 = fmaxf(m0, mx0);
        const float mn1 = fmaxf(m1, mx1);
        const float a0 = __expf(m0 - mn0);
        const float a1 = __expf(m1 - mn1);

        float rs0 = 0.0f, rs1 = 0.0f;
#pragma unroll
        for (int ni = 0; ni < 8; ni++) {
            s[ni][0] = __expf(s[ni][0] - mn0);
            s[ni][1] = __expf(s[ni][1] - mn0);
            s[ni][2] = __expf(s[ni][2] - mn1);
            s[ni][3] = __expf(s[ni][3] - mn1);
            rs0 += s[ni][0] + s[ni][1];
            rs1 += s[ni][2] + s[ni][3];
        }
        rs0 += __shfl_xor_sync(0xffffffffu, rs0, 1);
        rs0 += __shfl_xor_sync(0xffffffffu, rs0, 2);
        rs1 += __shfl_xor_sync(0xffffffffu, rs1, 1);
        rs1 += __shfl_xor_sync(0xffffffffu, rs1, 2);

        l0 = l0 * a0 + rs0;
        l1 = l1 * a1 + rs1;
        m0 = mn0;
        m1 = mn1;

#pragma unroll
        for (int ni = 0; ni < 8; ni++) {
            o[ni][0] *= a0; o[ni][1] *= a0;
            o[ni][2] *= a1; o[ni][3] *= a1;
        }

        __syncthreads();   // all warps done reading K-frag before P overwrites

        // Store P fragments (warp-local region of KPs)
#pragma unroll
        for (int ni = 0; ni < 8; ni++) {
#pragma unroll
            for (int e = 0; e < 4; e++) {
                const int kc = 2 * c + (e & 1);
                const int c_t = kc & 3;
                const int half_k = kc >> 2;
                const uint32_t lane_t = (uint32_t)(r * 4 + c_t);
                const int val = (e >> 1) + 2 * half_k;
                const uint32_t word = (uint32_t)((w * 8 + ni) * 128)
                                    + ((lane_t * 4) ^ (((lane_t >> 2) & 7) << 2)) + val;
                KPs[word] = f2tf(s[ni][e]);
            }
        }
        __syncwarp();

        // O += P @ V
#pragma unroll
        for (int ks = 0; ks < 8; ks++) {
            uint4 af = *(const uint4*)&KPs[(w * 8 + ks) * 128 + pSwz];
#pragma unroll
            for (int ni = 0; ni < 8; ni++) {
                uint2 bf = *(const uint2*)&Vs[(ni * 8 + ks) * 64 + (kSwz ^ (8 * (ni & 3)))];
                mma_tf32(o[ni], (const uint32_t*)&af, (const uint32_t*)&bf);
            }
        }
        __syncthreads();   // before next iter overwrites KPs/Vs
    }

    // Finalize and write to g_y (tf32 bits) in ORIGINAL token order
    const float i0 = 1.0f / l0;
    const float i1 = 1.0f / l1;
    const int lq0 = nq0 * T_ + tq0;
    const int lq1 = nq1 * T_ + tq1;
    uint32_t* y0 = &g_y[((size_t)b * L_ + lq0) * C_ + h * D_];
    uint32_t* y1 = &g_y[((size_t)b * L_ + lq1) * C_ + h * D_];
#pragma unroll
    for (int ni = 0; ni < 8; ni++) {
        const int col = ni * 8 + c * 2;
        *(uint2*)&y0[col] = make_uint2(f2tf(o[ni][0] * i0), f2tf(o[ni][1] * i0));
        *(uint2*)&y1[col] = make_uint2(f2tf(o[ni][2] * i1), f2tf(o[ni][3] * i1));
    }
}

extern "C" void kernel_launch(void* const* d_in, const int* in_sizes, int n_in,
                              void* d_out, int out_size) {
    const float* x  = (const float*)d_in[0];
    const float* Wq = (const float*)d_in[1];
    const float* Wk = (const float*)d_in[2];
    const float* Wv = (const float*)d_in[3];
    const float* Wo = (const float*)d_in[4];
    const float* bt = (const float*)d_in[5];
    const float* bp = (const float*)d_in[6];
    float* out = (float*)d_out;

    cudaFuncSetAttribute(gemm_tc<1>, cudaFuncAttributeMaxDynamicSharedMemorySize, GSMEM_BYTES);
    cudaFuncSetAttribute(gemm_tc<0>, cudaFuncAttributeMaxDynamicSharedMemorySize, GSMEM_BYTES);

    gemm_tc<1><<<dim3(12, 96), 128, GSMEM_BYTES>>>(x, Wq, Wk, Wv, nullptr);
    attn_tc<<<dim3(L_ / 64, B_ * Hh), 128>>>(bt, bp);
    gemm_tc<0><<<dim3(4, 96), 128, GSMEM_BYTES>>>(nullptr, Wo, nullptr, nullptr, out);
}

// round 8
// speedup vs baseline: 1.0422x; 1.0422x over previous
#include <cuda_runtime.h>
#include <cuda_bf16.h>
#include <math.h>
#include <stdint.h>

// Problem constants
#define B_   16
#define Hh   8
#define T_   48
#define Np   16
#define C_   512
#define D_   64
#define L_   768           // Np * T_
#define M_   (B_ * L_)     // 12288 rows

// Scratch — all tf32 bit patterns (converted at producer side)
__device__ uint32_t g_q[(size_t)B_ * Hh * D_ * L_];   // [b][h][d][l']  (t-major l')
__device__ uint32_t g_k[(size_t)B_ * Hh * D_ * L_];   // [b][h][d][l']
__device__ uint32_t g_v[(size_t)B_ * Hh * L_ * D_];   // [b][h][l'][d]
__device__ uint32_t g_y[(size_t)B_ * L_ * C_];        // [b][l][c]  (original l order)

__device__ __forceinline__ uint32_t f2tf(float f) {
    uint32_t u;
    asm("cvt.rna.tf32.f32 %0, %1;" : "=r"(u) : "f"(f));
    return u;
}

__device__ __forceinline__ void mma_tf32(float* d, const uint32_t* a, const uint32_t* b) {
    asm volatile(
        "mma.sync.aligned.m16n8k8.row.col.f32.tf32.tf32.f32 "
        "{%0,%1,%2,%3}, {%4,%5,%6,%7}, {%8,%9}, {%0,%1,%2,%3};"
        : "+f"(d[0]), "+f"(d[1]), "+f"(d[2]), "+f"(d[3])
        : "r"(a[0]), "r"(a[1]), "r"(a[2]), "r"(a[3]), "r"(b[0]), "r"(b[1]));
}

// ---------------------------------------------------------------------------
// Tensor-core tf32 GEMM, R4 loop structure (single buffer, 2 syncs/iter,
// register prefetch) + fragment-native conflict-free B smem layout.
// MODE 0: out = g_y(tf32 bits) @ W0        grid (4, 96)
// MODE 1: fused QKV: x @ {Wq,Wk,Wv}        grid (12, 96), wsel = n0g>>9
// Block 128 threads (4 warps 2x2), tile 128x128, K-step 32, 16 iters.
// ---------------------------------------------------------------------------
template <int MODE>
__global__ __launch_bounds__(128) void gemm_tc(const float* __restrict__ X,
                                               const float* __restrict__ W0,
                                               const float* __restrict__ W1,
                                               const float* __restrict__ W2,
                                               float* __restrict__ Cout) {
    __shared__ uint32_t Asf[8 * 4 * 132];   // A fragment-native, 4224 words
    __shared__ uint32_t Bsf[16 * 4 * 64];   // B fragment-native, 4096 words

    const int n0g = blockIdx.x * 128;
    const float* W;
    int wsel = 0;
    if (MODE == 1) {
        wsel = n0g >> 9;
        W = (wsel == 0) ? W0 : (wsel == 1) ? W1 : W2;
    } else {
        W = W0;
    }
    const int n0 = (MODE == 1) ? (n0g & 511) : n0g;
    const int m0 = blockIdx.y * 128;

    const int tid = threadIdx.x;
    const int lane = tid & 31;
    const int w = tid >> 5;
    const int wr = w & 1;
    const int wc = w >> 1;
    const int r = lane >> 2;
    const int c = lane & 3;

    float acc[4][8][4] = {};

    // A-load mapping
    const int s_a = tid >> 3;           // 0..15
    const int c4_a = (tid & 7) * 4;     // 0..28
    const int a_chunk = (tid & 7) >> 1;
    const int a_val = (s_a >> 3) + 2 * (tid & 1);
    const int a_lanebase = (s_a & 7) * 16;

    // B-load mapping (fragment-native, attn-style)
    const int ld_bn = tid & 15;         // column group (8 cols)
    const int ld_bs = tid >> 4;         // 0..7 (row within 8-row band)
    const int b_cc2 = (ld_bs & 3) * 2;
    const int b_val = ld_bs >> 2;
    const int b_xor = 8 * (ld_bn & 3);

    uint4 aU[8];
    uint4 bU[8];

    // prologue: load k0 = 0
#pragma unroll
    for (int f = 0; f < 8; f++) {
        if (MODE == 0) {
            aU[f] = *(const uint4*)&g_y[(size_t)(m0 + f * 16 + s_a) * C_ + c4_a];
        } else {
            float4 v = *(const float4*)&X[(size_t)(m0 + f * 16 + s_a) * C_ + c4_a];
            aU[f] = make_uint4(f2tf(v.x), f2tf(v.y), f2tf(v.z), f2tf(v.w));
        }
    }
#pragma unroll
    for (int it = 0; it < 4; it++) {
        float4 v0 = *(const float4*)&W[(size_t)(it * 8 + ld_bs) * C_ + n0 + ld_bn * 8];
        float4 v1 = *(const float4*)&W[(size_t)(it * 8 + ld_bs) * C_ + n0 + ld_bn * 8 + 4];
        bU[it * 2]     = make_uint4(f2tf(v0.x), f2tf(v0.y), f2tf(v0.z), f2tf(v0.w));
        bU[it * 2 + 1] = make_uint4(f2tf(v1.x), f2tf(v1.y), f2tf(v1.z), f2tf(v1.w));
    }

    for (int k0 = 0; k0 < C_; k0 += 32) {
        // STS from prefetch regs
#pragma unroll
        for (int f = 0; f < 8; f++) {
            const uint32_t av[4] = {aU[f].x, aU[f].y, aU[f].z, aU[f].w};
            const int abase = (f * 4 + a_chunk) * 132 + a_lanebase + a_val;
#pragma unroll
            for (int j = 0; j < 4; j++) Asf[abase + j * 4] = av[j];
        }
#pragma unroll
        for (int it = 0; it < 4; it++) {
            const uint32_t bv[8] = {bU[it*2].x, bU[it*2].y, bU[it*2].z, bU[it*2].w,
                                    bU[it*2+1].x, bU[it*2+1].y, bU[it*2+1].z, bU[it*2+1].w};
            const int wb = (ld_bn * 4 + it) * 64 + b_val;
#pragma unroll
            for (int j = 0; j < 8; j++) Bsf[wb + ((8 * j + b_cc2) ^ b_xor)] = bv[j];
        }
        __syncthreads();

        // prefetch next k-step
        if (k0 + 32 < C_) {
            const int k1 = k0 + 32;
#pragma unroll
            for (int f = 0; f < 8; f++) {
                if (MODE == 0) {
                    aU[f] = *(const uint4*)&g_y[(size_t)(m0 + f * 16 + s_a) * C_ + k1 + c4_a];
                } else {
                    float4 v = *(const float4*)&X[(size_t)(m0 + f * 16 + s_a) * C_ + k1 + c4_a];
                    aU[f] = make_uint4(f2tf(v.x), f2tf(v.y), f2tf(v.z), f2tf(v.w));
                }
            }
#pragma unroll
            for (int it = 0; it < 4; it++) {
                float4 v0 = *(const float4*)&W[(size_t)(k1 + it * 8 + ld_bs) * C_ + n0 + ld_bn * 8];
                float4 v1 = *(const float4*)&W[(size_t)(k1 + it * 8 + ld_bs) * C_ + n0 + ld_bn * 8 + 4];
                bU[it * 2]     = make_uint4(f2tf(v0.x), f2tf(v0.y), f2tf(v0.z), f2tf(v0.w));
                bU[it * 2 + 1] = make_uint4(f2tf(v1.x), f2tf(v1.y), f2tf(v1.z), f2tf(v1.w));
            }
        }

        // compute 4 k-steps of 8
#pragma unroll
        for (int ks = 0; ks < 4; ks++) {
            uint4 afr[4];
#pragma unroll
            for (int mi = 0; mi < 4; mi++)
                afr[mi] = *(const uint4*)&Asf[((wr * 4 + mi) * 4 + ks) * 132 + lane * 4];
            uint2 bfr[8];
#pragma unroll
            for (int ni = 0; ni < 8; ni++) {
                const int ng = wc * 8 + ni;
                bfr[ni] = *(const uint2*)&Bsf[(ng * 4 + ks) * 64 + ((lane * 2) ^ (8 * (ng & 3)))];
            }
#pragma unroll
            for (int mi = 0; mi < 4; mi++)
#pragma unroll
                for (int ni = 0; ni < 8; ni++)
                    mma_tf32(acc[mi][ni], (const uint32_t*)&afr[mi], (const uint32_t*)&bfr[ni]);
        }
        __syncthreads();
    }

    const float scale = (MODE == 1 && wsel == 0) ? 0.125f : 1.0f;
    const int c2 = c * 2;

#pragma unroll
    for (int mi = 0; mi < 4; mi++) {
#pragma unroll
        for (int ni = 0; ni < 8; ni++) {
#pragma unroll
            for (int e = 0; e < 4; e++) {
                const int m = m0 + wr * 64 + mi * 16 + r + (e >> 1) * 8;
                const int cc = n0 + wc * 64 + ni * 8 + c2 + (e & 1);
                const float val = acc[mi][ni][e] * scale;
                if (MODE == 0) {
                    Cout[(size_t)m * C_ + cc] = val;
                } else {
                    const int b = m / L_;
                    const int l = m - b * L_;
                    const int n = l / T_;
                    const int t = l - n * T_;
                    const int lp = t * Np + n;
                    const int h = cc >> 6;
                    const int d = cc & 63;
                    if (wsel == 0)
                        g_q[(((size_t)(b * Hh + h)) * D_ + d) * L_ + lp] = f2tf(val);
                    else if (wsel == 1)
                        g_k[(((size_t)(b * Hh + h)) * D_ + d) * L_ + lp] = f2tf(val);
                    else
                        g_v[(((size_t)(b * Hh + h)) * L_ + lp) * D_ + d] = f2tf(val);
                }
            }
        }
    }
}

// ---------------------------------------------------------------------------
// Tensor-core flash attention; q/k/v arrive as tf32 bits (no cvt on load).
// Grid: (12 q-tiles, 128 bh). Block: 128 threads (4 warps, 16 q-rows each).
// ---------------------------------------------------------------------------
__global__ __launch_bounds__(128) void attn_tc(const float* __restrict__ bt_tab,
                                               const float* __restrict__ bp_tab) {
    __shared__ uint32_t KPs[4096];   // K-frag; later P-frag
    __shared__ uint32_t Vs[4096];    // V-frag
    __shared__ float bt_s[95];
    __shared__ float bp_s[31];

    const int qt = 11 - blockIdx.x;    // long blocks first
    const int bh = blockIdx.y;
    const int b = bh >> 3;
    const int h = bh & 7;

    const uint32_t* qg = g_q + (size_t)bh * D_ * L_;
    const uint32_t* kg = g_k + (size_t)bh * D_ * L_;
    const uint32_t* vg = g_v + (size_t)bh * L_ * D_;

    const int tid = threadIdx.x;
    const int lane = tid & 31;
    const int w = tid >> 5;
    const int r = lane >> 2;   // 0..7
    const int c = lane & 3;    // 0..3

    if (tid < 95) bt_s[tid] = bt_tab[tid * Hh + h];
    if (tid < 31) bp_s[tid] = bp_tab[tid * Hh + h];

    const int row0 = qt * 64 + w * 16 + r;
    const int row1 = row0 + 8;
    const int tq0 = row0 >> 4, nq0 = row0 & 15;
    const int tq1 = row1 >> 4, nq1 = row1 & 15;

    // Q fragments (raw tf32 bits)
    uint32_t qf[8][4];
#pragma unroll
    for (int ks = 0; ks < 8; ks++) {
        const int d0 = ks * 8 + c;
        qf[ks][0] = qg[(size_t)d0 * L_ + row0];
        qf[ks][1] = qg[(size_t)d0 * L_ + row1];
        qf[ks][2] = qg[(size_t)(d0 + 4) * L_ + row0];
        qf[ks][3] = qg[(size_t)(d0 + 4) * L_ + row1];
    }

    // loader-thread constants
    const int ld_s = tid >> 3;          // 0..15
    const int ld_ni = tid & 7;          // column group
    const int ld_c8 = ld_ni * 8;
    const int ld_xor = 8 * (ld_ni & 3);

    float m0 = -1e30f, m1 = -1e30f;
    float l0 = 0.0f, l1 = 0.0f;
    float o[8][4] = {};

    // prefetch kt=0 tiles
    uint4 kR[8], vR[8];
#pragma unroll
    for (int it = 0; it < 4; it++) {
        const int rr = it * 16 + ld_s;
        kR[it * 2]     = *(const uint4*)&kg[(size_t)rr * L_ + ld_c8];
        kR[it * 2 + 1] = *(const uint4*)&kg[(size_t)rr * L_ + ld_c8 + 4];
        vR[it * 2]     = *(const uint4*)&vg[(size_t)rr * D_ + ld_c8];
        vR[it * 2 + 1] = *(const uint4*)&vg[(size_t)rr * D_ + ld_c8 + 4];
    }

    __syncthreads();   // bias tables visible

    const uint32_t pSwz = (uint32_t)(lane * 4) ^ ((uint32_t)(r & 7) << 2);
    const uint32_t kSwz = (uint32_t)(lane * 2);

    for (int kt = 0; kt <= qt; kt++) {
        // STS K/V fragments from prefetch regs
#pragma unroll
        for (int it = 0; it < 4; it++) {
            const int rr = it * 16 + ld_s;
            const int ks = rr >> 3;
            const int dc = rr & 7;
            const int cc2 = (dc & 3) * 2;
            const int val = dc >> 2;
            const int kbase = (ld_ni * 8 + ks) * 64 + val;
            const uint32_t kv[8] = {kR[it*2].x, kR[it*2].y, kR[it*2].z, kR[it*2].w,
                                    kR[it*2+1].x, kR[it*2+1].y, kR[it*2+1].z, kR[it*2+1].w};
            const uint32_t vv[8] = {vR[it*2].x, vR[it*2].y, vR[it*2].z, vR[it*2].w,
                                    vR[it*2+1].x, vR[it*2+1].y, vR[it*2+1].z, vR[it*2+1].w};
#pragma unroll
            for (int j = 0; j < 8; j++) {
                const int off = ((8 * j + cc2) ^ ld_xor);
                KPs[kbase + off] = kv[j];
                Vs[kbase + off] = vv[j];
            }
        }
        __syncthreads();

        // prefetch next tile
        if (kt < qt) {
            const int kn = (kt + 1) * 64;
#pragma unroll
            for (int it = 0; it < 4; it++) {
                const int rr = it * 16 + ld_s;
                kR[it * 2]     = *(const uint4*)&kg[(size_t)rr * L_ + kn + ld_c8];
                kR[it * 2 + 1] = *(const uint4*)&kg[(size_t)rr * L_ + kn + ld_c8 + 4];
                vR[it * 2]     = *(const uint4*)&vg[(size_t)(kn + rr) * D_ + ld_c8];
                vR[it * 2 + 1] = *(const uint4*)&vg[(size_t)(kn + rr) * D_ + ld_c8 + 4];
            }
        }

        // S = Q K
        float s[8][4] = {};
#pragma unroll
        for (int ks = 0; ks < 8; ks++) {
#pragma unroll
            for (int ni = 0; ni < 8; ni++) {
                uint2 bf = *(const uint2*)&KPs[(ni * 8 + ks) * 64 + (kSwz ^ (8 * (ni & 3)))];
                mma_tf32(s[ni], qf[ks], (const uint32_t*)&bf);
            }
        }

        // Bias + causal mask (mask only on diagonal tile)
        const bool diag = (kt == qt);
#pragma unroll
        for (int ni = 0; ni < 8; ni++) {
#pragma unroll
            for (int e = 0; e < 4; e++) {
                const int col = ni * 8 + c * 2 + (e & 1);
                const int lpk = kt * 64 + col;
                const int tk = lpk >> 4;
                const int nk = lpk & 15;
                const int tq = (e < 2) ? tq0 : tq1;
                const int nq = (e < 2) ? nq0 : nq1;
                s[ni][e] += bt_s[47 + tk - tq] + bp_s[15 + nk - nq];
                if (diag && tk > tq) s[ni][e] = -1e30f;
            }
        }

        // Online softmax
        float mx0 = -1e30f, mx1 = -1e30f;
#pragma unroll
        for (int ni = 0; ni < 8; ni++) {
            mx0 = fmaxf(mx0, fmaxf(s[ni][0], s[ni][1]));
            mx1 = fmaxf(mx1, fmaxf(s[ni][2], s[ni][3]));
        }
        mx0 = fmaxf(mx0, __shfl_xor_sync(0xffffffffu, mx0, 1));
        mx0 = fmaxf(mx0, __shfl_xor_sync(0xffffffffu, mx0, 2));
        mx1 = fmaxf(mx1, __shfl_xor_sync(0xffffffffu, mx1, 1));
        mx1 = fmaxf(mx1, __shfl_xor_sync(0xffffffffu, mx1, 2));

        const float mn0 = fmaxf(m0, mx0);
        const float mn1 = fmaxf(m1, mx1);
        const float a0 = __expf(m0 - mn0);
        const float a1 = __expf(m1 - mn1);

        float rs0 = 0.0f, rs1 = 0.0f;
#pragma unroll
        for (int ni = 0; ni < 8; ni++) {
            s[ni][0] = __expf(s[ni][0] - mn0);
            s[ni][1] = __expf(s[ni][1] - mn0);
            s[ni][2] = __expf(s[ni][2] - mn1);
            s[ni][3] = __expf(s[ni][3] - mn1);
            rs0 += s[ni][0] + s[ni][1];
            rs1 += s[ni][2] + s[ni][3];
        }
        rs0 += __shfl_xor_sync(0xffffffffu, rs0, 1);
        rs0 += __shfl_xor_sync(0xffffffffu, rs0, 2);
        rs1 += __shfl_xor_sync(0xffffffffu, rs1, 1);
        rs1 += __shfl_xor_sync(0xffffffffu, rs1, 2);

        l0 = l0 * a0 + rs0;
        l1 = l1 * a1 + rs1;
        m0 = mn0;
        m1 = mn1;

#pragma unroll
        for (int ni = 0; ni < 8; ni++) {
            o[ni][0] *= a0; o[ni][1] *= a0;
            o[ni][2] *= a1; o[ni][3] *= a1;
        }

        __syncthreads();   // all warps done reading K-frag before P overwrites

        // Store P fragments (warp-local region of KPs)
#pragma unroll
        for (int ni = 0; ni < 8; ni++) {
#pragma unroll
            for (int e = 0; e < 4; e++) {
                const int kc = 2 * c + (e & 1);
                const int c_t = kc & 3;
                const int half_k = kc >> 2;
                const uint32_t lane_t = (uint32_t)(r * 4 + c_t);
                const int val = (e >> 1) + 2 * half_k;
                const uint32_t word = (uint32_t)((w * 8 + ni) * 128)
                                    + ((lane_t * 4) ^ (((lane_t >> 2) & 7) << 2)) + val;
                KPs[word] = f2tf(s[ni][e]);
            }
        }
        __syncwarp();

        // O += P @ V
#pragma unroll
        for (int ks = 0; ks < 8; ks++) {
            uint4 af = *(const uint4*)&KPs[(w * 8 + ks) * 128 + pSwz];
#pragma unroll
            for (int ni = 0; ni < 8; ni++) {
                uint2 bf = *(const uint2*)&Vs[(ni * 8 + ks) * 64 + (kSwz ^ (8 * (ni & 3)))];
                mma_tf32(o[ni], (const uint32_t*)&af, (const uint32_t*)&bf);
            }
        }
        __syncthreads();   // before next iter overwrites KPs/Vs
    }

    // Finalize and write to g_y (tf32 bits) in ORIGINAL token order
    const float i0 = 1.0f / l0;
    const float i1 = 1.0f / l1;
    const int lq0 = nq0 * T_ + tq0;
    const int lq1 = nq1 * T_ + tq1;
    uint32_t* y0 = &g_y[((size_t)b * L_ + lq0) * C_ + h * D_];
    uint32_t* y1 = &g_y[((size_t)b * L_ + lq1) * C_ + h * D_];
#pragma unroll
    for (int ni = 0; ni < 8; ni++) {
        const int col = ni * 8 + c * 2;
        *(uint2*)&y0[col] = make_uint2(f2tf(o[ni][0] * i0), f2tf(o[ni][1] * i0));
        *(uint2*)&y1[col] = make_uint2(f2tf(o[ni][2] * i1), f2tf(o[ni][3] * i1));
    }
}

extern "C" void kernel_launch(void* const* d_in, const int* in_sizes, int n_in,
                              void* d_out, int out_size) {
    const float* x  = (const float*)d_in[0];
    const float* Wq = (const float*)d_in[1];
    const float* Wk = (const float*)d_in[2];
    const float* Wv = (const float*)d_in[3];
    const float* Wo = (const float*)d_in[4];
    const float* bt = (const float*)d_in[5];
    const float* bp = (const float*)d_in[6];
    float* out = (float*)d_out;

    gemm_tc<1><<<dim3(12, 96), 128>>>(x, Wq, Wk, Wv, nullptr);
    attn_tc<<<dim3(L_ / 64, B_ * Hh), 128>>>(bt, bp);
    gemm_tc<0><<<dim3(4, 96), 128>>>(nullptr, Wo, nullptr, nullptr, out);
}

// round 12
// speedup vs baseline: 1.1955x; 1.1471x over previous
#include <cuda_runtime.h>
#include <cuda_bf16.h>
#include <math.h>
#include <stdint.h>

// Problem constants
#define B_   16
#define Hh   8
#define T_   48
#define Np   16
#define C_   512
#define D_   64
#define L_   768           // Np * T_
#define M_   (B_ * L_)     // 12288 rows

// Scratch — all tf32 bit patterns (converted once at pack time / producer side)
__device__ __align__(16) uint32_t g_x[(size_t)M_ * C_];             // packed input x
__device__ __align__(16) uint32_t g_w[(size_t)4 * C_ * C_];         // packed Wq,Wk,Wv,Wo
__device__ __align__(16) uint32_t g_q[(size_t)B_ * Hh * D_ * L_];   // [b][h][d][l']  (t-major)
__device__ __align__(16) uint32_t g_k[(size_t)B_ * Hh * D_ * L_];   // [b][h][d][l']
__device__ __align__(16) uint32_t g_v[(size_t)B_ * Hh * L_ * D_];   // [b][h][l'][d]
__device__ __align__(16) uint32_t g_y[(size_t)B_ * L_ * C_];        // [b][l][c]  (orig order)

__device__ __forceinline__ uint32_t f2tf(float f) {
    uint32_t u;
    asm("cvt.rna.tf32.f32 %0, %1;" : "=r"(u) : "f"(f));
    return u;
}

__device__ __forceinline__ void mma_tf32(float* d, const uint32_t* a, const uint32_t* b) {
    asm volatile(
        "mma.sync.aligned.m16n8k8.row.col.f32.tf32.tf32.f32 "
        "{%0,%1,%2,%3}, {%4,%5,%6,%7}, {%8,%9}, {%0,%1,%2,%3};"
        : "+f"(d[0]), "+f"(d[1]), "+f"(d[2]), "+f"(d[3])
        : "r"(a[0]), "r"(a[1]), "r"(a[2]), "r"(a[3]), "r"(b[0]), "r"(b[1]));
}

// ---------------------------------------------------------------------------
// Pack pass: convert x and the 4 weight matrices to tf32 bits once.
// ---------------------------------------------------------------------------
#define NX4 ((M_ * C_) / 4)       // 1,572,864 float4 granules of x
#define NW4 ((C_ * C_) / 4)       // 65,536 per weight matrix

__global__ __launch_bounds__(256) void pack_tf32(const float* __restrict__ x,
                                                 const float* __restrict__ Wq,
                                                 const float* __restrict__ Wk,
                                                 const float* __restrict__ Wv,
                                                 const float* __restrict__ Wo) {
    const int i = blockIdx.x * 256 + threadIdx.x;
    float4 v;
    uint4* dst;
    if (i < NX4) {
        v = ((const float4*)x)[i];
        dst = (uint4*)g_x + i;
    } else {
        const int j = i - NX4;
        if (j >= 4 * NW4) return;
        const int ws = j >> 16;                 // 65536 float4 per W
        const int off = j & (NW4 - 1);
        const float* W = (ws == 0) ? Wq : (ws == 1) ? Wk : (ws == 2) ? Wv : Wo;
        v = ((const float4*)W)[off];
        dst = (uint4*)g_w + j;
    }
    *dst = make_uint4(f2tf(v.x), f2tf(v.y), f2tf(v.z), f2tf(v.w));
}

// ---------------------------------------------------------------------------
// Tensor-core tf32 GEMM — R4 structure (single buffer, 2 syncs/iter, register
// prefetch, fragment-native A pad-132, B [k][n] pad-136), all data pre-packed
// as tf32 bits: zero cvt in the loop.
// MODE 0: out = g_y @ Wo               grid (4, 96)
// MODE 1: fused QKV: g_x @ {Wq,Wk,Wv}  grid (12, 96), wsel = n0g>>9
// Block 128 threads (4 warps 2x2), tile 128x128, K-step 32, 16 iters.
// ---------------------------------------------------------------------------
template <int MODE>
__global__ __launch_bounds__(128) void gemm_tc(float* __restrict__ Cout) {
    __shared__ uint32_t Asf[8 * 4 * 132];   // [m_tile][k_step] fragment chunks
    __shared__ uint32_t Bsf[32 * 136];      // [k][n], pad 136 (conflict-free)

    const uint32_t* Ain = (MODE == 0) ? g_y : g_x;
    const int n0g = blockIdx.x * 128;
    const int wsel = (MODE == 1) ? (n0g >> 9) : 3;
    const uint32_t* W = g_w + (size_t)wsel * C_ * C_;
    const int n0 = (MODE == 1) ? (n0g & 511) : n0g;
    const int m0 = blockIdx.y * 128;

    const int tid = threadIdx.x;
    const int lane = tid & 31;
    const int w = tid >> 5;
    const int wr = w & 1;
    const int wc = w >> 1;
    const int r = lane >> 2;
    const int c = lane & 3;

    float acc[4][8][4] = {};

    // A-load mapping: row = f*16 + s_a, cols c4_a..+3
    const int s_a = tid >> 3;           // 0..15
    const int c4_a = (tid & 7) * 4;     // 0..28
    // B-load mapping: krow = f*4 + kr_b, cols u_b*4..+3
    const int kr_b = tid >> 5;          // 0..3
    const int u_b = tid & 31;

    // A STS target pieces
    const int a_chunk = (tid & 7) >> 1;            // k_step
    const int a_val = (s_a >> 3) + 2 * (tid & 1);  // half_m + 2*half_k
    const int a_lanebase = (s_a & 7) * 16;

    uint4 aR[8], bR[8];
#pragma unroll
    for (int f = 0; f < 8; f++) {
        aR[f] = *(const uint4*)&Ain[(size_t)(m0 + f * 16 + s_a) * C_ + c4_a];
        bR[f] = *(const uint4*)&W[(size_t)(f * 4 + kr_b) * C_ + n0 + u_b * 4];
    }

    for (int k0 = 0; k0 < C_; k0 += 32) {
        // STS phase (from prefetch regs) — pure moves, no cvt
#pragma unroll
        for (int f = 0; f < 8; f++) {
            const uint32_t av[4] = {aR[f].x, aR[f].y, aR[f].z, aR[f].w};
            const int abase = (f * 4 + a_chunk) * 132 + a_lanebase + a_val;
#pragma unroll
            for (int j = 0; j < 4; j++) Asf[abase + j * 4] = av[j];
            *(uint4*)&Bsf[(f * 4 + kr_b) * 136 + u_b * 4] = bR[f];
        }
        __syncthreads();

        if (k0 + 32 < C_) {
            const int k1 = k0 + 32;
#pragma unroll
            for (int f = 0; f < 8; f++) {
                aR[f] = *(const uint4*)&Ain[(size_t)(m0 + f * 16 + s_a) * C_ + k1 + c4_a];
                bR[f] = *(const uint4*)&W[(size_t)(k1 + f * 4 + kr_b) * C_ + n0 + u_b * 4];
            }
        }

        // compute 4 k-steps of 8
#pragma unroll
        for (int ks = 0; ks < 4; ks++) {
            uint4 afr[4];
#pragma unroll
            for (int mi = 0; mi < 4; mi++)
                afr[mi] = *(const uint4*)&Asf[((wr * 4 + mi) * 4 + ks) * 132 + lane * 4];
            uint32_t bfr[8][2];
            const int kc = ks * 8 + c;
#pragma unroll
            for (int ni = 0; ni < 8; ni++) {
                const int nb = wc * 64 + ni * 8 + r;
                bfr[ni][0] = Bsf[kc * 136 + nb];
                bfr[ni][1] = Bsf[(kc + 4) * 136 + nb];
            }
#pragma unroll
            for (int mi = 0; mi < 4; mi++)
#pragma unroll
                for (int ni = 0; ni < 8; ni++)
                    mma_tf32(acc[mi][ni], (const uint32_t*)&afr[mi], bfr[ni]);
        }
        __syncthreads();
    }

    const float scale = (MODE == 1 && wsel == 0) ? 0.125f : 1.0f;
    const int c2 = c * 2;

#pragma unroll
    for (int mi = 0; mi < 4; mi++) {
#pragma unroll
        for (int ni = 0; ni < 8; ni++) {
#pragma unroll
            for (int e = 0; e < 4; e++) {
                const int m = m0 + wr * 64 + mi * 16 + r + (e >> 1) * 8;
                const int cc = n0 + wc * 64 + ni * 8 + c2 + (e & 1);
                const float val = acc[mi][ni][e] * scale;
                if (MODE == 0) {
                    Cout[(size_t)m * C_ + cc] = val;
                } else {
                    const int b = m / L_;
                    const int l = m - b * L_;
                    const int n = l / T_;
                    const int t = l - n * T_;
                    const int lp = t * Np + n;
                    const int h = cc >> 6;
                    const int d = cc & 63;
                    if (wsel == 0)
                        g_q[(((size_t)(b * Hh + h)) * D_ + d) * L_ + lp] = f2tf(val);
                    else if (wsel == 1)
                        g_k[(((size_t)(b * Hh + h)) * D_ + d) * L_ + lp] = f2tf(val);
                    else
                        g_v[(((size_t)(b * Hh + h)) * L_ + lp) * D_ + d] = f2tf(val);
                }
            }
        }
    }
}

// ---------------------------------------------------------------------------
// Tensor-core flash attention; q/k/v arrive as tf32 bits (no cvt on load).
// Grid: (12 q-tiles, 128 bh). Block: 128 threads (4 warps, 16 q-rows each).
// (Identical logic to the R8 version that passed.)
// ---------------------------------------------------------------------------
__global__ __launch_bounds__(128) void attn_tc(const float* __restrict__ bt_tab,
                                               const float* __restrict__ bp_tab) {
    __shared__ uint32_t KPs[4096];   // K-frag; later P-frag
    __shared__ uint32_t Vs[4096];    // V-frag
    __shared__ float bt_s[95];
    __shared__ float bp_s[31];

    const int qt = 11 - blockIdx.x;    // long blocks first
    const int bh = blockIdx.y;
    const int b = bh >> 3;
    const int h = bh & 7;

    const uint32_t* qg = g_q + (size_t)bh * D_ * L_;
    const uint32_t* kg = g_k + (size_t)bh * D_ * L_;
    const uint32_t* vg = g_v + (size_t)bh * L_ * D_;

    const int tid = threadIdx.x;
    const int lane = tid & 31;
    const int w = tid >> 5;
    const int r = lane >> 2;   // 0..7
    const int c = lane & 3;    // 0..3

    if (tid < 95) bt_s[tid] = bt_tab[tid * Hh + h];
    if (tid < 31) bp_s[tid] = bp_tab[tid * Hh + h];

    const int row0 = qt * 64 + w * 16 + r;
    const int row1 = row0 + 8;
    const int tq0 = row0 >> 4, nq0 = row0 & 15;
    const int tq1 = row1 >> 4, nq1 = row1 & 15;

    // Q fragments (raw tf32 bits)
    uint32_t qf[8][4];
#pragma unroll
    for (int ks = 0; ks < 8; ks++) {
        const int d0 = ks * 8 + c;
        qf[ks][0] = qg[(size_t)d0 * L_ + row0];
        qf[ks][1] = qg[(size_t)d0 * L_ + row1];
        qf[ks][2] = qg[(size_t)(d0 + 4) * L_ + row0];
        qf[ks][3] = qg[(size_t)(d0 + 4) * L_ + row1];
    }

    // loader-thread constants
    const int ld_s = tid >> 3;          // 0..15
    const int ld_ni = tid & 7;          // column group
    const int ld_c8 = ld_ni * 8;
    const int ld_xor = 8 * (ld_ni & 3);

    float m0 = -1e30f, m1 = -1e30f;
    float l0 = 0.0f, l1 = 0.0f;
    float o[8][4] = {};

    // prefetch kt=0 tiles
    uint4 kR[8], vR[8];
#pragma unroll
    for (int it = 0; it < 4; it++) {
        const int rr = it * 16 + ld_s;
        kR[it * 2]     = *(const uint4*)&kg[(size_t)rr * L_ + ld_c8];
        kR[it * 2 + 1] = *(const uint4*)&kg[(size_t)rr * L_ + ld_c8 + 4];
        vR[it * 2]     = *(const uint4*)&vg[(size_t)rr * D_ + ld_c8];
        vR[it * 2 + 1] = *(const uint4*)&vg[(size_t)rr * D_ + ld_c8 + 4];
    }

    __syncthreads();   // bias tables visible

    const uint32_t pSwz = (uint32_t)(lane * 4) ^ ((uint32_t)(r & 7) << 2);
    const uint32_t kSwz = (uint32_t)(lane * 2);

    for (int kt = 0; kt <= qt; kt++) {
        // STS K/V fragments from prefetch regs
#pragma unroll
        for (int it = 0; it < 4; it++) {
            const int rr = it * 16 + ld_s;
            const int ks = rr >> 3;
            const int dc = rr & 7;
            const int cc2 = (dc & 3) * 2;
            const int val = dc >> 2;
            const int kbase = (ld_ni * 8 + ks) * 64 + val;
            const uint32_t kv[8] = {kR[it*2].x, kR[it*2].y, kR[it*2].z, kR[it*2].w,
                                    kR[it*2+1].x, kR[it*2+1].y, kR[it*2+1].z, kR[it*2+1].w};
            const uint32_t vv[8] = {vR[it*2].x, vR[it*2].y, vR[it*2].z, vR[it*2].w,
                                    vR[it*2+1].x, vR[it*2+1].y, vR[it*2+1].z, vR[it*2+1].w};
#pragma unroll
            for (int j = 0; j < 8; j++) {
                const int off = ((8 * j + cc2) ^ ld_xor);
                KPs[kbase + off] = kv[j];
                Vs[kbase + off] = vv[j];
            }
        }
        __syncthreads();

        // prefetch next tile
        if (kt < qt) {
            const int kn = (kt + 1) * 64;
#pragma unroll
            for (int it = 0; it < 4; it++) {
                const int rr = it * 16 + ld_s;
                kR[it * 2]     = *(const uint4*)&kg[(size_t)rr * L_ + kn + ld_c8];
                kR[it * 2 + 1] = *(const uint4*)&kg[(size_t)rr * L_ + kn + ld_c8 + 4];
                vR[it * 2]     = *(const uint4*)&vg[(size_t)(kn + rr) * D_ + ld_c8];
                vR[it * 2 + 1] = *(const uint4*)&vg[(size_t)(kn + rr) * D_ + ld_c8 + 4];
            }
        }

        // S = Q K
        float s[8][4] = {};
#pragma unroll
        for (int ks = 0; ks < 8; ks++) {
#pragma unroll
            for (int ni = 0; ni < 8; ni++) {
                uint2 bf = *(const uint2*)&KPs[(ni * 8 + ks) * 64 + (kSwz ^ (8 * (ni & 3)))];
                mma_tf32(s[ni], qf[ks], (const uint32_t*)&bf);
            }
        }

        // Bias + causal mask (mask only on diagonal tile)
        const bool diag = (kt == qt);
#pragma unroll
        for (int ni = 0; ni < 8; ni++) {
#pragma unroll
            for (int e = 0; e < 4; e++) {
                const int col = ni * 8 + c * 2 + (e & 1);
                const int lpk = kt * 64 + col;
                const int tk = lpk >> 4;
                const int nk = lpk & 15;
                const int tq = (e < 2) ? tq0 : tq1;
                const int nq = (e < 2) ? nq0 : nq1;
                s[ni][e] += bt_s[47 + tk - tq] + bp_s[15 + nk - nq];
                if (diag && tk > tq) s[ni][e] = -1e30f;
            }
        }

        // Online softmax
        float mx0 = -1e30f, mx1 = -1e30f;
#pragma unroll
        for (int ni = 0; ni < 8; ni++) {
            mx0 = fmaxf(mx0, fmaxf(s[ni][0], s[ni][1]));
            mx1 = fmaxf(mx1, fmaxf(s[ni][2], s[ni][3]));
        }
        mx0 = fmaxf(mx0, __shfl_xor_sync(0xffffffffu, mx0, 1));
        mx0 = fmaxf(mx0, __shfl_xor_sync(0xffffffffu, mx0, 2));
        mx1 = fmaxf(mx1, __shfl_xor_sync(0xffffffffu, mx1, 1));
        mx1 = fmaxf(mx1, __shfl_xor_sync(0xffffffffu, mx1, 2));

        const float mn0 = fmaxf(m0, mx0);
        const float mn1 = fmaxf(m1, mx1);
        const float a0 = __expf(m0 - mn0);
        const float a1 = __expf(m1 - mn1);

        float rs0 = 0.0f, rs1 = 0.0f;
#pragma unroll
        for (int ni = 0; ni < 8; ni++) {
            s[ni][0] = __expf(s[ni][0] - mn0);
            s[ni][1] = __expf(s[ni][1] - mn0);
            s[ni][2] = __expf(s[ni][2] - mn1);
            s[ni][3] = __expf(s[ni][3] - mn1);
            rs0 += s[ni][0] + s[ni][1];
            rs1 += s[ni][2] + s[ni][3];
        }
        rs0 += __shfl_xor_sync(0xffffffffu, rs0, 1);
        rs0 += __shfl_xor_sync(0xffffffffu, rs0, 2);
        rs1 += __shfl_xor_sync(0xffffffffu, rs1, 1);
        rs1 += __shfl_xor_sync(0xffffffffu, rs1, 2);

        l0 = l0 * a0 + rs0;
        l1 = l1 * a1 + rs1;
        m0 = mn0;
        m1 = mn1;

#pragma unroll
        for (int ni = 0; ni < 8; ni++) {
            o[ni][0] *= a0; o[ni][1] *= a0;
            o[ni][2] *= a1; o[ni][3] *= a1;
        }

        __syncthreads();   // all warps done reading K-frag before P overwrites

        // Store P fragments (warp-local region of KPs)
#pragma unroll
        for (int ni = 0; ni < 8; ni++) {
#pragma unroll
            for (int e = 0; e < 4; e++) {
                const int kc = 2 * c + (e & 1);
                const int c_t = kc & 3;
                const int half_k = kc >> 2;
                const uint32_t lane_t = (uint32_t)(r * 4 + c_t);
                const int val = (e >> 1) + 2 * half_k;
                const uint32_t word = (uint32_t)((w * 8 + ni) * 128)
                                    + ((lane_t * 4) ^ (((lane_t >> 2) & 7) << 2)) + val;
                KPs[word] = f2tf(s[ni][e]);
            }
        }
        __syncwarp();

        // O += P @ V
#pragma unroll
        for (int ks = 0; ks < 8; ks++) {
            uint4 af = *(const uint4*)&KPs[(w * 8 + ks) * 128 + pSwz];
#pragma unroll
            for (int ni = 0; ni < 8; ni++) {
                uint2 bf = *(const uint2*)&Vs[(ni * 8 + ks) * 64 + (kSwz ^ (8 * (ni & 3)))];
                mma_tf32(o[ni], (const uint32_t*)&af, (const uint32_t*)&bf);
            }
        }
        __syncthreads();   // before next iter overwrites KPs/Vs
    }

    // Finalize and write to g_y (tf32 bits) in ORIGINAL token order
    const float i0 = 1.0f / l0;
    const float i1 = 1.0f / l1;
    const int lq0 = nq0 * T_ + tq0;
    const int lq1 = nq1 * T_ + tq1;
    uint32_t* y0 = &g_y[((size_t)b * L_ + lq0) * C_ + h * D_];
    uint32_t* y1 = &g_y[((size_t)b * L_ + lq1) * C_ + h * D_];
#pragma unroll
    for (int ni = 0; ni < 8; ni++) {
        const int col = ni * 8 + c * 2;
        *(uint2*)&y0[col] = make_uint2(f2tf(o[ni][0] * i0), f2tf(o[ni][1] * i0));
        *(uint2*)&y1[col] = make_uint2(f2tf(o[ni][2] * i1), f2tf(o[ni][3] * i1));
    }
}

extern "C" void kernel_launch(void* const* d_in, const int* in_sizes, int n_in,
                              void* d_out, int out_size) {
    const float* x  = (const float*)d_in[0];
    const float* Wq = (const float*)d_in[1];
    const float* Wk = (const float*)d_in[2];
    const float* Wv = (const float*)d_in[3];
    const float* Wo = (const float*)d_in[4];
    const float* bt = (const float*)d_in[5];
    const float* bp = (const float*)d_in[6];
    float* out = (float*)d_out;

    pack_tf32<<<(NX4 + 4 * NW4 + 255) / 256, 256>>>(x, Wq, Wk, Wv, Wo);
    gemm_tc<1><<<dim3(12, 96), 128>>>(nullptr);
    attn_tc<<<dim3(L_ / 64, B_ * Hh), 128>>>(bt, bp);
    gemm_tc<0><<<dim3(4, 96), 128>>>(out);
}

// round 16
// speedup vs baseline: 1.8191x; 1.5216x over previous
#include <cuda_runtime.h>
#include <cuda_fp16.h>
#include <math.h>
#include <stdint.h>

// Problem constants
#define B_   16
#define Hh   8
#define T_   48
#define Np   16
#define C_   512
#define D_   64
#define L_   768           // Np * T_
#define M_   (B_ * L_)     // 12288 rows

// Scratch — fp16 at rest (packed once / produced by kernels)
__device__ __align__(16) __half   g_x[(size_t)M_ * C_];            // x, row-major half
__device__ __align__(16) __half   g_w[(size_t)4 * C_ * C_];        // W', kpair-major: [ws][kp(256)][n(512)] half2 words
__device__ __align__(16) uint32_t g_q[(size_t)B_ * Hh * L_ * 32];  // [bh][l'][dpair]  (t-major l')
__device__ __align__(16) uint32_t g_k[(size_t)B_ * Hh * L_ * 32];  // [bh][l'][dpair]
__device__ __align__(16) __half   g_v[(size_t)B_ * Hh * D_ * L_];  // [bh][d][l']
__device__ __align__(16) __half   g_y[(size_t)M_ * C_];            // [b*l][c], row-major half

__device__ __forceinline__ uint32_t f2h2(float lo, float hi) {
    __half2 h = __floats2half2_rn(lo, hi);
    return *(uint32_t*)&h;
}

__device__ __forceinline__ void mma_f16(float* d, const uint32_t* a, const uint32_t* b) {
    asm volatile(
        "mma.sync.aligned.m16n8k16.row.col.f32.f16.f16.f32 "
        "{%0,%1,%2,%3}, {%4,%5,%6,%7}, {%8,%9}, {%0,%1,%2,%3};"
        : "+f"(d[0]), "+f"(d[1]), "+f"(d[2]), "+f"(d[3])
        : "r"(a[0]), "r"(a[1]), "r"(a[2]), "r"(a[3]), "r"(b[0]), "r"(b[1]));
}

// ---------------------------------------------------------------------------
// Pack pass: x -> half row-major; W -> half kpair-major (word (kp,n) = half2
// of W[2kp][n], W[2kp+1][n]) so GEMM B-fragments are native loads.
// ---------------------------------------------------------------------------
#define NXH ((M_ * C_) / 8)       // 786432 uint4 granules of x
#define NWH ((C_ * C_) / 8)       // 32768 uint4 granules per W

__global__ __launch_bounds__(256) void pack_f16(const float* __restrict__ x,
                                                const float* __restrict__ Wq,
                                                const float* __restrict__ Wk,
                                                const float* __restrict__ Wv,
                                                const float* __restrict__ Wo) {
    const int i = blockIdx.x * 256 + threadIdx.x;
    if (i < NXH) {
        float4 v0 = ((const float4*)x)[i * 2];
        float4 v1 = ((const float4*)x)[i * 2 + 1];
        ((uint4*)g_x)[i] = make_uint4(f2h2(v0.x, v0.y), f2h2(v0.z, v0.w),
                                      f2h2(v1.x, v1.y), f2h2(v1.z, v1.w));
    } else {
        const int j = i - NXH;
        if (j >= 4 * NWH) return;
        const int ws = j >> 15;
        const int g = j & (NWH - 1);
        const int kp = g >> 7;               // 0..255
        const int n4 = (g & 127) * 4;        // 0..508
        const float* W = (ws == 0) ? Wq : (ws == 1) ? Wk : (ws == 2) ? Wv : Wo;
        float4 va = *(const float4*)&W[(size_t)(2 * kp) * C_ + n4];
        float4 vb = *(const float4*)&W[(size_t)(2 * kp + 1) * C_ + n4];
        uint4* dst = (uint4*)(g_w + (size_t)ws * C_ * C_);
        dst[kp * 128 + (g & 127)] = make_uint4(f2h2(va.x, vb.x), f2h2(va.y, vb.y),
                                               f2h2(va.z, vb.z), f2h2(va.w, vb.w));
    }
}

// ---------------------------------------------------------------------------
// fp16 tensor-core GEMM, R4 loop structure, fragment-native A, kpair-major B.
// MODE 0: out = g_y @ Wo'              grid (4, 96)
// MODE 1: fused QKV: g_x @ {Wq,Wk,Wv}' grid (12, 96), wsel = n0g>>9
// Block 128 threads (4 warps 2x2), tile 128x128, K-step 32 (2 k16), 16 iters.
// ---------------------------------------------------------------------------
template <int MODE>
__global__ __launch_bounds__(128) void gemm_tc(float* __restrict__ Cout) {
    __shared__ uint32_t Asf[8 * 2 * 132];   // 2112 words: [m_tile][ks] fragment chunks
    __shared__ uint32_t Bsf[16 * 136];      // 2176 words: [kpair][n] pad 136

    const __half* Ah = (MODE == 0) ? g_y : g_x;
    const int n0g = blockIdx.x * 128;
    const int wsel = (MODE == 1) ? (n0g >> 9) : 3;
    const uint32_t* Wp = (const uint32_t*)(g_w + (size_t)wsel * C_ * C_);
    const int n0 = (MODE == 1) ? (n0g & 511) : n0g;
    const int m0 = blockIdx.y * 128;

    const int tid = threadIdx.x;
    const int lane = tid & 31;
    const int w = tid >> 5;
    const int wr = w & 1;
    const int wc = w >> 1;
    const int r = lane >> 2;
    const int c = lane & 3;

    float acc[4][8][4] = {};

    // A-load mapping: row = f*16 + s_a, halves k-offset ha..ha+3 (uint2 = 2 kpairs)
    const int s_a = tid >> 3;           // 0..15
    const int ha = (tid & 7) * 4;       // half offset within 32-k step
    // A STS constants for its two kpairs
    const int kp0 = (tid & 7) * 2;
    const int r8 = s_a & 7;
    const int hm = s_a >> 3;
    // B-load mapping
    const int kr_b = tid >> 5;          // 0..3
    const int u_b = tid & 31;

    uint2 aR[8];
    uint4 bR[4];

#pragma unroll
    for (int f = 0; f < 8; f++)
        aR[f] = *(const uint2*)&Ah[(size_t)(m0 + f * 16 + s_a) * C_ + ha];
#pragma unroll
    for (int u = 0; u < 4; u++)
        bR[u] = *(const uint4*)&Wp[(u * 4 + kr_b) * C_ + n0 + u_b * 4];

    for (int k0 = 0; k0 < C_; k0 += 32) {
        // STS from prefetch regs
#pragma unroll
        for (int f = 0; f < 8; f++) {
#pragma unroll
            for (int j = 0; j < 2; j++) {
                const int kp = kp0 + j;
                const int ks = kp >> 3;
                const int pc = kp & 7;
                Asf[(f * 2 + ks) * 132 + r8 * 16 + (pc & 3) * 4 + hm + 2 * (pc >> 2)]
                    = (j == 0) ? aR[f].x : aR[f].y;
            }
        }
#pragma unroll
        for (int u = 0; u < 4; u++)
            *(uint4*)&Bsf[(u * 4 + kr_b) * 136 + u_b * 4] = bR[u];
        __syncthreads();

        if (k0 + 32 < C_) {
            const int k1 = k0 + 32;
#pragma unroll
            for (int f = 0; f < 8; f++)
                aR[f] = *(const uint2*)&Ah[(size_t)(m0 + f * 16 + s_a) * C_ + k1 + ha];
#pragma unroll
            for (int u = 0; u < 4; u++)
                bR[u] = *(const uint4*)&Wp[((k1 >> 1) + u * 4 + kr_b) * C_ + n0 + u_b * 4];
        }

        // compute 2 k16 steps
#pragma unroll
        for (int ks = 0; ks < 2; ks++) {
            uint4 afr[4];
#pragma unroll
            for (int mi = 0; mi < 4; mi++)
                afr[mi] = *(const uint4*)&Asf[((wr * 4 + mi) * 2 + ks) * 132 + lane * 4];
            uint32_t bfr[8][2];
            const int kc = ks * 8 + c;
#pragma unroll
            for (int ni = 0; ni < 8; ni++) {
                const int nb = wc * 64 + ni * 8 + r;
                bfr[ni][0] = Bsf[kc * 136 + nb];
                bfr[ni][1] = Bsf[(kc + 4) * 136 + nb];
            }
#pragma unroll
            for (int mi = 0; mi < 4; mi++)
#pragma unroll
                for (int ni = 0; ni < 8; ni++)
                    mma_f16(acc[mi][ni], (const uint32_t*)&afr[mi], bfr[ni]);
        }
        __syncthreads();
    }

    const float scale = (MODE == 1 && wsel == 0) ? 0.125f : 1.0f;

#pragma unroll
    for (int mi = 0; mi < 4; mi++) {
#pragma unroll
        for (int ni = 0; ni < 8; ni++) {
#pragma unroll
            for (int eh = 0; eh < 2; eh++) {
                const int m = m0 + wr * 64 + mi * 16 + r + eh * 8;
                const int cc = n0 + wc * 64 + ni * 8 + c * 2;
                const float v0 = acc[mi][ni][eh * 2] * scale;
                const float v1 = acc[mi][ni][eh * 2 + 1] * scale;
                if (MODE == 0) {
                    Cout[(size_t)m * C_ + cc] = v0;
                    Cout[(size_t)m * C_ + cc + 1] = v1;
                } else {
                    const int b = m / L_;
                    const int l = m - b * L_;
                    const int n = l / T_;
                    const int t = l - n * T_;
                    const int lp = t * Np + n;
                    const int h = cc >> 6;
                    const int d = cc & 63;
                    if (wsel == 0)
                        g_q[((size_t)(b * Hh + h) * L_ + lp) * 32 + (d >> 1)] = f2h2(v0, v1);
                    else if (wsel == 1)
                        g_k[((size_t)(b * Hh + h) * L_ + lp) * 32 + (d >> 1)] = f2h2(v0, v1);
                    else {
                        g_v[((size_t)(b * Hh + h) * D_ + d) * L_ + lp] = __float2half(v0);
                        g_v[((size_t)(b * Hh + h) * D_ + d + 1) * L_ + lp] = __float2half(v1);
                    }
                }
            }
        }
    }
}

// ---------------------------------------------------------------------------
// fp16 tensor-core flash attention.
// Grid: (12 q-tiles, 128 bh). Block: 128 threads (4 warps, 16 q-rows each).
// q,k [l'][dpair-words]; v [d][l'] halves. Ks buffer reused for P fragments.
// Vs stride = 72 (> 64 d-columns; 8c+r bank permutation => conflict-free).
// ---------------------------------------------------------------------------
__global__ __launch_bounds__(128) void attn_tc(const float* __restrict__ bt_tab,
                                               const float* __restrict__ bp_tab) {
    __shared__ uint32_t Ks[64 * 36];   // K: [key][dpair] stride 36; later P: [q][keypair]
    __shared__ uint32_t Vs[32 * 72];   // V: [keypair][d] stride 72
    __shared__ float bt_s[95];
    __shared__ float bp_s[31];

    const int qt = 11 - blockIdx.x;    // long blocks first
    const int bh = blockIdx.y;
    const int b = bh >> 3;
    const int h = bh & 7;

    const uint32_t* qgw = g_q + (size_t)bh * L_ * 32;
    const uint32_t* kgw = g_k + (size_t)bh * L_ * 32;
    const __half* vh = g_v + (size_t)bh * D_ * L_;

    const int tid = threadIdx.x;
    const int lane = tid & 31;
    const int w = tid >> 5;
    const int r = lane >> 2;   // 0..7
    const int c = lane & 3;    // 0..3

    if (tid < 95) bt_s[tid] = bt_tab[tid * Hh + h];
    if (tid < 31) bp_s[tid] = bp_tab[tid * Hh + h];

    const int row0 = qt * 64 + w * 16 + r;
    const int row1 = row0 + 8;
    const int tq0 = row0 >> 4, nq0 = row0 & 15;
    const int tq1 = row1 >> 4, nq1 = row1 & 15;

    // Q fragments: (row, dpair) half2 words; 4 k16 steps over D=64
    uint32_t qf[4][4];
#pragma unroll
    for (int ks = 0; ks < 4; ks++) {
        qf[ks][0] = qgw[row0 * 32 + ks * 8 + c];
        qf[ks][1] = qgw[row1 * 32 + ks * 8 + c];
        qf[ks][2] = qgw[row0 * 32 + ks * 8 + c + 4];
        qf[ks][3] = qgw[row1 * 32 + ks * 8 + c + 4];
    }

    // loader constants: K rows = keys, V rows = d
    const int ld_row = tid >> 1;        // 0..63
    const int ld_idx = (tid & 1) * 4;   // uint4 index base within row

    float m0 = -1e30f, m1 = -1e30f;
    float l0 = 0.0f, l1 = 0.0f;
    float o[8][4] = {};

    // prefetch kt=0
    uint4 kR[4], vR[4];
#pragma unroll
    for (int u = 0; u < 4; u++) {
        kR[u] = ((const uint4*)kgw)[(size_t)(0 * 64 + ld_row) * 8 + ld_idx + u];
        vR[u] = ((const uint4*)vh)[(size_t)ld_row * 96 + 0 * 8 + ld_idx + u];
    }

    __syncthreads();   // bias tables visible

    for (int kt = 0; kt <= qt; kt++) {
        // STS K/V from prefetch regs
#pragma unroll
        for (int u = 0; u < 4; u++) {
            const uint32_t kc4[4] = {kR[u].x, kR[u].y, kR[u].z, kR[u].w};
            const uint32_t vc4[4] = {vR[u].x, vR[u].y, vR[u].z, vR[u].w};
            const int base4 = (ld_idx + u) * 4;
#pragma unroll
            for (int j = 0; j < 4; j++) {
                Ks[ld_row * 36 + base4 + j] = kc4[j];
                Vs[(base4 + j) * 72 + ld_row] = vc4[j];
            }
        }
        __syncthreads();

        // prefetch next tile
        if (kt < qt) {
            const int kn = kt + 1;
#pragma unroll
            for (int u = 0; u < 4; u++) {
                kR[u] = ((const uint4*)kgw)[(size_t)(kn * 64 + ld_row) * 8 + ld_idx + u];
                vR[u] = ((const uint4*)vh)[(size_t)ld_row * 96 + kn * 8 + ld_idx + u];
            }
        }

        // S = Q K^T (k = d, 4 k16 steps)
        float s[8][4] = {};
#pragma unroll
        for (int ks = 0; ks < 4; ks++) {
#pragma unroll
            for (int ni = 0; ni < 8; ni++) {
                uint32_t bf[2];
                bf[0] = Ks[(ni * 8 + r) * 36 + ks * 8 + c];
                bf[1] = Ks[(ni * 8 + r) * 36 + ks * 8 + c + 4];
                mma_f16(s[ni], qf[ks], bf);
            }
        }

        // Bias + causal mask (mask only on diagonal tile)
        const bool diag = (kt == qt);
#pragma unroll
        for (int ni = 0; ni < 8; ni++) {
#pragma unroll
            for (int e = 0; e < 4; e++) {
                const int col = ni * 8 + c * 2 + (e & 1);
                const int lpk = kt * 64 + col;
                const int tk = lpk >> 4;
                const int nk = lpk & 15;
                const int tq = (e < 2) ? tq0 : tq1;
                const int nq = (e < 2) ? nq0 : nq1;
                s[ni][e] += bt_s[47 + tk - tq] + bp_s[15 + nk - nq];
                if (diag && tk > tq) s[ni][e] = -1e30f;
            }
        }

        // Online softmax (reduce over lane quads via xor 1,2)
        float mx0 = -1e30f, mx1 = -1e30f;
#pragma unroll
        for (int ni = 0; ni < 8; ni++) {
            mx0 = fmaxf(mx0, fmaxf(s[ni][0], s[ni][1]));
            mx1 = fmaxf(mx1, fmaxf(s[ni][2], s[ni][3]));
        }
        mx0 = fmaxf(mx0, __shfl_xor_sync(0xffffffffu, mx0, 1));
        mx0 = fmaxf(mx0, __shfl_xor_sync(0xffffffffu, mx0, 2));
        mx1 = fmaxf(mx1, __shfl_xor_sync(0xffffffffu, mx1, 1));
        mx1 = fmaxf(mx1, __shfl_xor_sync(0xffffffffu, mx1, 2));

        const float mn0 = fmaxf(m0, mx0);
        const float mn1 = fmaxf(m1, mx1);
        const float a0 = __expf(m0 - mn0);
        const float a1 = __expf(m1 - mn1);

        float rs0 = 0.0f, rs1 = 0.0f;
#pragma unroll
        for (int ni = 0; ni < 8; ni++) {
            s[ni][0] = __expf(s[ni][0] - mn0);
            s[ni][1] = __expf(s[ni][1] - mn0);
            s[ni][2] = __expf(s[ni][2] - mn1);
            s[ni][3] = __expf(s[ni][3] - mn1);
            rs0 += s[ni][0] + s[ni][1];
            rs1 += s[ni][2] + s[ni][3];
        }
        rs0 += __shfl_xor_sync(0xffffffffu, rs0, 1);
        rs0 += __shfl_xor_sync(0xffffffffu, rs0, 2);
        rs1 += __shfl_xor_sync(0xffffffffu, rs1, 1);
        rs1 += __shfl_xor_sync(0xffffffffu, rs1, 2);

        l0 = l0 * a0 + rs0;
        l1 = l1 * a1 + rs1;
        m0 = mn0;
        m1 = mn1;

#pragma unroll
        for (int ni = 0; ni < 8; ni++) {
            o[ni][0] *= a0; o[ni][1] *= a0;
            o[ni][2] *= a1; o[ni][3] *= a1;
        }

        __syncthreads();   // all warps done reading Ks before P overwrites

        // Store P fragments into Ks buffer: [q-row][keypair], keypair = ni*4 + c
#pragma unroll
        for (int ni = 0; ni < 8; ni++) {
            Ks[(w * 16 + r) * 36 + ni * 4 + c] = f2h2(s[ni][0], s[ni][1]);
            Ks[(w * 16 + r + 8) * 36 + ni * 4 + c] = f2h2(s[ni][2], s[ni][3]);
        }
        __syncwarp();

        // O += P @ V (k = key, 4 k16 steps over 64 keys)
#pragma unroll
        for (int ks = 0; ks < 4; ks++) {
            uint32_t af[4];
            af[0] = Ks[(w * 16 + r) * 36 + ks * 8 + c];
            af[1] = Ks[(w * 16 + r + 8) * 36 + ks * 8 + c];
            af[2] = Ks[(w * 16 + r) * 36 + ks * 8 + c + 4];
            af[3] = Ks[(w * 16 + r + 8) * 36 + ks * 8 + c + 4];
#pragma unroll
            for (int ni = 0; ni < 8; ni++) {
                uint32_t bf[2];
                bf[0] = Vs[(ks * 8 + c) * 72 + ni * 8 + r];
                bf[1] = Vs[(ks * 8 + c + 4) * 72 + ni * 8 + r];
                mma_f16(o[ni], af, bf);
            }
        }
        __syncthreads();   // before next iter overwrites Ks/Vs
    }

    // Finalize and write y (half) in ORIGINAL token order
    const float i0 = 1.0f / l0;
    const float i1 = 1.0f / l1;
    const int lq0 = nq0 * T_ + tq0;
    const int lq1 = nq1 * T_ + tq1;
    uint32_t* yw = (uint32_t*)g_y;
#pragma unroll
    for (int ni = 0; ni < 8; ni++) {
        const int wd = h * 32 + ni * 4 + c;
        yw[(size_t)(b * L_ + lq0) * 256 + wd] = f2h2(o[ni][0] * i0, o[ni][1] * i0);
        yw[(size_t)(b * L_ + lq1) * 256 + wd] = f2h2(o[ni][2] * i1, o[ni][3] * i1);
    }
}

extern "C" void kernel_launch(void* const* d_in, const int* in_sizes, int n_in,
                              void* d_out, int out_size) {
    const float* x  = (const float*)d_in[0];
    const float* Wq = (const float*)d_in[1];
    const float* Wk = (const float*)d_in[2];
    const float* Wv = (const float*)d_in[3];
    const float* Wo = (const float*)d_in[4];
    const float* bt = (const float*)d_in[5];
    const float* bp = (const float*)d_in[6];
    float* out = (float*)d_out;

    pack_f16<<<(NXH + 4 * NWH + 255) / 256, 256>>>(x, Wq, Wk, Wv, Wo);
    gemm_tc<1><<<dim3(12, 96), 128>>>(nullptr);
    attn_tc<<<dim3(L_ / 64, B_ * Hh), 128>>>(bt, bp);
    gemm_tc<0><<<dim3(4, 96), 128>>>(out);
}